// round 11
// baseline (speedup 1.0000x reference)
#include <cuda_runtime.h>
#include <cuda_fp16.h>
#include <math_constants.h>
#include <cstdint>

#define BATCH 512
#define SEQ   256
#define EMBD  384
#define HEAD  64
#define NQ    192            // Q|K|V concatenated output columns
#define TK    32             // K chunk
#define KCH   (EMBD / TK)    // 12

// Scratch (allocation-free rule: device globals)
__device__ __half g_Wh[NQ * EMBD];      // n-major concat weights [n][k], half
__device__ float  g_bc[NQ];             // concat bias (fp32)

// ---------------------------------------------------------------------------
// helpers
// ---------------------------------------------------------------------------
__device__ __forceinline__ uint32_t packh2(float lo, float hi) {
    __half2 h = __floats2half2_rn(lo, hi);
    return reinterpret_cast<uint32_t&>(h);
}
#define CP_ASYNC16(dst, src) \
    asm volatile("cp.async.cg.shared.global [%0], [%1], 16;" \
                 :: "r"((uint32_t)(dst)), "l"(src) : "memory")
#define CP_COMMIT() asm volatile("cp.async.commit_group;" ::: "memory")
#define CP_WAIT(n)  asm volatile("cp.async.wait_group %0;" :: "n"(n) : "memory")

__device__ __forceinline__ uint32_t smem_u32(const void* p) {
    uint32_t a;
    asm("{ .reg .u64 t; cvta.to.shared.u64 t, %1; cvt.u32.u64 %0, t; }"
        : "=r"(a) : "l"(p));
    return a;
}
__device__ __forceinline__ void ldm_x4(uint32_t* r, uint32_t addr) {
    asm volatile("ldmatrix.sync.aligned.m8n8.x4.shared.b16 {%0,%1,%2,%3}, [%4];"
        : "=r"(r[0]), "=r"(r[1]), "=r"(r[2]), "=r"(r[3]) : "r"(addr));
}
__device__ __forceinline__ void mma_f16(float* d, const uint32_t* a, const uint32_t* b) {
    asm volatile(
        "mma.sync.aligned.m16n8k16.row.col.f32.f16.f16.f32 "
        "{%0,%1,%2,%3}, {%4,%5,%6,%7}, {%8,%9}, {%0,%1,%2,%3};"
        : "+f"(d[0]), "+f"(d[1]), "+f"(d[2]), "+f"(d[3])
        : "r"(a[0]), "r"(a[1]), "r"(a[2]), "r"(a[3]), "r"(b[0]), "r"(b[1]));
}

// ---------------------------------------------------------------------------
// Kernel 0: concat weights to n-major half [n][k], concat bias fp32
// ---------------------------------------------------------------------------
__global__ __launch_bounds__(256) void prep_w(
    const float* __restrict__ Wq, const float* __restrict__ bq,
    const float* __restrict__ Wk, const float* __restrict__ bk,
    const float* __restrict__ Wv, const float* __restrict__ bv)
{
    int idx = blockIdx.x * 256 + threadIdx.x;
    if (idx < NQ * EMBD) {
        int n = idx / EMBD;
        int k = idx - n * EMBD;
        const float* W = (n < 64) ? Wq : (n < 128) ? Wk : Wv;
        g_Wh[idx] = __float2half_rn(W[k * HEAD + (n & 63)]);
    }
    if (idx < NQ) {
        const float* bb = (idx < 64) ? bq : (idx < 128) ? bk : bv;
        g_bc[idx] = bb[idx & 63];
    }
}

// ---------------------------------------------------------------------------
// Fused kernel: one CTA = one batch. 512 threads / 16 warps.
// Phase 1: QKV projection with a 3-stage cp.async pipeline (stage 2 of each
//          buffer aliased over the Ks/Qs-head and Vt regions, which are dead
//          until the epilogue). One barrier per chunk.
// Phase 2: causal flash attention (unchanged R10 body).
//
// smem layout (bytes):
//   Ks [256][72]h      @ 0        36864   (phase1: A-stage2 @ 0..40960)
//   Qs [256][72]h      @ 36864    36864   (head 4KB shared with A-stage2)
//   Vt [64][264]h      @ 73728    33792   (phase1: B-stage2 @ 73728..95232)
//   Ax 2x[256][40]f32  @ 107520   81920   (A stages 0,1)
//   Bw 2x[192][56]h    @ 189440   43008   (B stages 0,1)
//   total                         232448  (= 227 KB)
// ---------------------------------------------------------------------------
#define SKH  72            // half stride, Ks/Qs rows
#define VTS  264           // half stride, Vt rows
#define XS_F (SEQ * 40)    // floats per A buffer (10240)
#define WS_H (NQ * 56)     // halfs per B buffer (10752)
#define FUSED_SMEM 232448

__global__ __launch_bounds__(512) void fused_attn(
    const float* __restrict__ x, float* __restrict__ out)
{
    extern __shared__ char smb[];
    __half* Ks = (__half*)smb;                    // [256][72]
    __half* Qs = (__half*)smb + SEQ * SKH;        // [256][72]
    __half* Vt = (__half*)smb + 2 * SEQ * SKH;    // [64][264]

    const int b    = blockIdx.x;
    const int tid  = threadIdx.x;
    const int w    = tid >> 5;
    const int lane = tid & 31;
    const int g    = lane >> 2;
    const int tg   = lane & 3;
    const size_t brow = (size_t)b * SEQ;

    const uint32_t ks_b = smem_u32(Ks);
    const uint32_t qs_b = smem_u32(Qs);

    // ======================= Phase 1: QKV projection =======================
    {
        const int m_w = (w & 3) * 64;      // 4 M-warps cover 256 rows
        const int n_w = (w >> 2) * 48;     // 4 N-warps cover 192 cols

        // 3-stage buffers: stages 0,1 dedicated; stage 2 aliased over Ks/Vt.
        float*  const Abuf[3] = { (float*)(smb + 107520),
                                  (float*)(smb + 107520 + 40960),
                                  (float*)(smb + 0) };
        __half* const Bbuf[3] = { (__half*)(smb + 189440),
                                  (__half*)(smb + 189440 + 21504),
                                  (__half*)(smb + 73728) };
        const uint32_t AbufB[3] = { smem_u32(Abuf[0]), smem_u32(Abuf[1]),
                                    smem_u32(Abuf[2]) };
        const uint32_t BbufB[3] = { smem_u32(Bbuf[0]), smem_u32(Bbuf[1]),
                                    smem_u32(Bbuf[2]) };

        float acc[4][6][4];
        #pragma unroll
        for (int mb = 0; mb < 4; mb++)
            #pragma unroll
            for (int nb = 0; nb < 6; nb++)
                #pragma unroll
                for (int i = 0; i < 4; i++) acc[mb][nb][i] = 0.0f;

        // A: 256 rows x 8 16B-chunks = 2048, 4/thread.
        // B: 192 rows x 4 16B-chunks = 768, guarded 2/thread.
#define STAGE(kc, st) do {                                                     \
        const int _k0 = (kc) * TK;                                             \
        const uint32_t _ab = AbufB[st];                                        \
        const uint32_t _bb = BbufB[st];                                        \
        _Pragma("unroll")                                                      \
        for (int _j = 0; _j < 4; _j++) {                                       \
            int _idx = tid + _j * 512;                                         \
            int _r = _idx >> 3, _q = _idx & 7;                                 \
            uint32_t _ad = _ab + 4 * (_r * 40 + 4 * _q);                       \
            CP_ASYNC16(_ad, (const char*)(x + (brow + _r) * EMBD + _k0 + 4 * _q)); \
        }                                                                      \
        _Pragma("unroll")                                                      \
        for (int _j = 0; _j < 2; _j++) {                                       \
            int _idx = tid + _j * 512;                                         \
            if (_idx < 768) {                                                  \
                int _n = _idx >> 2, _c = _idx & 3;                             \
                uint32_t _bd = _bb + 2 * (_n * 56 + 8 * _c);                   \
                CP_ASYNC16(_bd, (const char*)(g_Wh + (size_t)_n * EMBD + _k0 + 8 * _c)); \
            }                                                                  \
        }                                                                      \
        CP_COMMIT();                                                           \
    } while (0)

        // prologue: two chunks in flight
        STAGE(0, 0);
        STAGE(1, 1);

        #pragma unroll
        for (int kc = 0; kc < KCH; kc++) {
            const int st = kc % 3;
            // group kc must be complete; {kc+1} (and soon kc+2) may be pending
            if (kc == KCH - 1) { CP_WAIT(0); } else { CP_WAIT(1); }
            __syncthreads();   // also: everyone finished reading buf (kc-1)%3

            if (kc + 2 < KCH) STAGE(kc + 2, (kc + 2) % 3);

            const float*  As = Abuf[st];
            const __half* Bs = Bbuf[st];

            #pragma unroll
            for (int s = 0; s < 2; s++) {
                const int ks = 16 * s;
                // A fragments for all 4 m-tiles (fp32 LDS.64 + pack)
                uint32_t AF[4][4];
                #pragma unroll
                for (int mb = 0; mb < 4; mb++) {
                    const int rb = m_w + 16 * mb;
                    float2 p0 = *(const float2*)(As + (rb + g)     * 40 + ks + 2 * tg);
                    float2 p1 = *(const float2*)(As + (rb + g + 8) * 40 + ks + 2 * tg);
                    float2 p2 = *(const float2*)(As + (rb + g)     * 40 + ks + 2 * tg + 8);
                    float2 p3 = *(const float2*)(As + (rb + g + 8) * 40 + ks + 2 * tg + 8);
                    AF[mb][0] = packh2(p0.x, p0.y);
                    AF[mb][1] = packh2(p1.x, p1.y);
                    AF[mb][2] = packh2(p2.x, p2.y);
                    AF[mb][3] = packh2(p3.x, p3.y);
                }
                // B fragments two n-tiles at a time
                #pragma unroll
                for (int p = 0; p < 3; p++) {
                    uint32_t bf[4];
                    const int n0 = n_w + 16 * p + g;
                    bf[0] = *(const uint32_t*)(Bs + n0 * 56 + ks + 2 * tg);
                    bf[1] = *(const uint32_t*)(Bs + n0 * 56 + ks + 2 * tg + 8);
                    bf[2] = *(const uint32_t*)(Bs + (n0 + 8) * 56 + ks + 2 * tg);
                    bf[3] = *(const uint32_t*)(Bs + (n0 + 8) * 56 + ks + 2 * tg + 8);
                    #pragma unroll
                    for (int mb = 0; mb < 4; mb++) {
                        mma_f16(acc[mb][2 * p],     AF[mb], bf);
                        mma_f16(acc[mb][2 * p + 1], AF[mb], bf + 2);
                    }
                }
            }
        }
#undef STAGE

        __syncthreads();   // all chunks computed; aliased regions now reusable

        // Epilogue: bias; Q scaled+half -> Qs, K half -> Ks, V -> Vt (transposed)
        const float qscale = 0.125f * 1.44269504088896340736f;  // SCALE*log2(e)
        #pragma unroll
        for (int nb = 0; nb < 6; nb++) {
            const int col = n_w + nb * 8 + tg * 2;
            const float2 bbv = *(const float2*)(g_bc + col);
            #pragma unroll
            for (int mb = 0; mb < 4; mb++) {
                #pragma unroll
                for (int h = 0; h < 2; h++) {
                    const int row = m_w + mb * 16 + g + h * 8;
                    float ox = acc[mb][nb][h * 2 + 0] + bbv.x;
                    float oy = acc[mb][nb][h * 2 + 1] + bbv.y;
                    if (col < 64) {
                        *(__half2*)(Qs + row * SKH + col) =
                            __floats2half2_rn(ox * qscale, oy * qscale);
                    } else if (col < 128) {
                        *(__half2*)(Ks + row * SKH + (col - 64)) =
                            __floats2half2_rn(ox, oy);
                    } else {
                        Vt[(col - 128) * VTS + row] = __float2half_rn(ox);
                        Vt[(col - 127) * VTS + row] = __float2half_rn(oy);
                    }
                }
            }
        }
    }
    __syncthreads();   // phase boundary: Qs/Ks/Vt complete and visible

    // ======================= Phase 2: flash attention ======================
    const int qw = (w < 8) ? w : 23 - w;   // per-SMSP block counts all = 34
    __half* Pw = Qs + qw * 16 * SKH;       // warp-private [16][72]
    const uint32_t pw_b = qs_b + qw * 16 * SKH * 2;
    const int lmat = lane >> 3, lr = lane & 7;

    // aQ fragments: 4 x ldmatrix.x4 (kt 0..3) from this warp's own Q rows
    uint32_t aQ[4][4];
    {
        const int row = (lmat & 1) * 8 + lr;
        #pragma unroll
        for (int kt = 0; kt < 4; kt++) {
            uint32_t addr = pw_b + 2 * (row * SKH + kt * 16 + (lmat >> 1) * 8);
            ldm_x4(aQ[kt], addr);
        }
    }

    float m_[2] = {-CUDART_INF_F, -CUDART_INF_F};
    float l_[2] = {0.0f, 0.0f};
    float O[8][4];
    #pragma unroll
    for (int nh = 0; nh < 8; nh++)
        #pragma unroll
        for (int e = 0; e < 4; e++) O[nh][e] = 0.0f;

    for (int j = 0; j <= qw; j++) {
        // ---- S = Q @ K_j^T  (16x16) ----
        float sc[2][4] = {{0, 0, 0, 0}, {0, 0, 0, 0}};
        #pragma unroll
        for (int kt = 0; kt < 4; kt++) {
            uint32_t bK[4];
            uint32_t addr = ks_b + 2 * ((16 * j + (lmat >> 1) * 8 + lr) * SKH
                                        + kt * 16 + (lmat & 1) * 8);
            ldm_x4(bK, addr);
            mma_f16(sc[0], aQ[kt], bK);
            mma_f16(sc[1], aQ[kt], bK + 2);
        }

        // ---- causal mask on diagonal block ----
        if (j == qw) {
            #pragma unroll
            for (int nt = 0; nt < 2; nt++)
                #pragma unroll
                for (int hh = 0; hh < 2; hh++)
                    #pragma unroll
                    for (int e = 0; e < 2; e++) {
                        const int rloc = 8 * hh + g;
                        const int cloc = 8 * nt + 2 * tg + e;
                        if (cloc > rloc) sc[nt][2 * hh + e] = -CUDART_INF_F;
                    }
        }

        // ---- online softmax (2 row states) ----
        #pragma unroll
        for (int hh = 0; hh < 2; hh++) {
            float rm = fmaxf(fmaxf(sc[0][2 * hh], sc[0][2 * hh + 1]),
                             fmaxf(sc[1][2 * hh], sc[1][2 * hh + 1]));
            rm = fmaxf(rm, __shfl_xor_sync(0xffffffffu, rm, 1));
            rm = fmaxf(rm, __shfl_xor_sync(0xffffffffu, rm, 2));
            const float nm = fmaxf(m_[hh], rm);
            const float cc = exp2f(m_[hh] - nm);     // 0 on first block
            m_[hh] = nm;
            l_[hh] *= cc;
            #pragma unroll
            for (int nh = 0; nh < 8; nh++) {
                O[nh][2 * hh]     *= cc;
                O[nh][2 * hh + 1] *= cc;
            }
            float rs = 0.0f;
            #pragma unroll
            for (int nt = 0; nt < 2; nt++)
                #pragma unroll
                for (int e = 0; e < 2; e++) {
                    float p = exp2f(sc[nt][2 * hh + e] - nm);
                    rs += p;
                    sc[nt][2 * hh + e] = p;
                }
            rs += __shfl_xor_sync(0xffffffffu, rs, 1);
            rs += __shfl_xor_sync(0xffffffffu, rs, 2);
            l_[hh] += rs;
        }

        // ---- P (half) -> warp-private smem ----
        #pragma unroll
        for (int hh = 0; hh < 2; hh++)
            #pragma unroll
            for (int nt = 0; nt < 2; nt++) {
                uint32_t pp = packh2(sc[nt][2 * hh], sc[nt][2 * hh + 1]);
                *(uint32_t*)(Pw + (8 * hh + g) * SKH + 8 * nt + 2 * tg) = pp;
            }
        __syncwarp();

        // ---- aP fragment (one ldmatrix.x4) ----
        uint32_t aP[4];
        {
            uint32_t addr = pw_b + 2 * (((lmat & 1) * 8 + lr) * SKH + (lmat >> 1) * 8);
            ldm_x4(aP, addr);
        }

        // ---- O += P @ V_j ----
        const int s0 = 16 * j + 2 * tg;
        #pragma unroll
        for (int nh = 0; nh < 8; nh++) {
            uint32_t bV[2];
            const int cv = 8 * nh + g;
            bV[0] = *(const uint32_t*)(Vt + cv * VTS + s0);
            bV[1] = *(const uint32_t*)(Vt + cv * VTS + s0 + 8);
            mma_f16(O[nh], aP, bV);
        }
        __syncwarp();
    }

    // ---- epilogue: normalize + store ----
    #pragma unroll
    for (int hh = 0; hh < 2; hh++) {
        const float inv = 1.0f / l_[hh];
        const size_t row = brow + qw * 16 + 8 * hh + g;
        #pragma unroll
        for (int nh = 0; nh < 8; nh++) {
            float2 o;
            o.x = O[nh][2 * hh]     * inv;
            o.y = O[nh][2 * hh + 1] * inv;
            *(float2*)(out + row * HEAD + 8 * nh + 2 * tg) = o;
        }
    }
}

// ---------------------------------------------------------------------------
extern "C" void kernel_launch(void* const* d_in, const int* in_sizes, int n_in,
                              void* d_out, int out_size)
{
    const float* x  = (const float*)d_in[0];
    const float* Wq = (const float*)d_in[1];
    const float* bq = (const float*)d_in[2];
    const float* Wk = (const float*)d_in[3];
    const float* bk = (const float*)d_in[4];
    const float* Wv = (const float*)d_in[5];
    const float* bv = (const float*)d_in[6];
    float* out = (float*)d_out;

    prep_w<<<(NQ * EMBD + 255) / 256, 256>>>(Wq, bq, Wk, bk, Wv, bv);

    cudaFuncSetAttribute(fused_attn,
                         cudaFuncAttributeMaxDynamicSharedMemorySize, FUSED_SMEM);
    fused_attn<<<BATCH, 512, FUSED_SMEM>>>(x, out);
}